// round 5
// baseline (speedup 1.0000x reference)
#include <cuda_runtime.h>
#include <cstdint>

#define N_NODES 50000
#define N_EDGES 600000
#define D_K     128
#define D_H1    128
#define D_H2    64

// ---------------- scratch (device globals: no allocation allowed) ----------
__device__ int   g_deg     [N_NODES];
__device__ float g_dinv    [N_NODES];
__device__ int   g_rowstart[N_NODES + 1];
__device__ int   g_cursor  [N_NODES];
__device__ int   g_csr_src [N_EDGES];
__device__ float g_csr_norm[N_EDGES];
__device__ __align__(16) float g_t1  [N_NODES * D_H1];   // x @ W1
__device__ __align__(16) float g_agg1[N_NODES * D_H1];   // aggregated layer-1
__device__ __align__(16) float g_t2  [N_NODES * D_H2];   // relu(agg1+b1) @ W2

__device__ __forceinline__ int clampi(int v) {
    return min(max(v, 0), N_NODES - 1);
}

// ---------------- degree -----------------------------------------------------
__global__ void k_init_deg() {
    int i = blockIdx.x * blockDim.x + threadIdx.x;
    if (i < N_NODES) g_deg[i] = 1;          // self-loop
}

__global__ void k_count_deg(const int* __restrict__ ei) {
    int e = blockIdx.x * blockDim.x + threadIdx.x;
    if (e < N_EDGES) atomicAdd(&g_deg[clampi(ei[N_EDGES + e])], 1);  // dst
}

// ---------------- single-block scan: rowstart/cursor/dinv -------------------
__global__ void __launch_bounds__(1024) k_scan() {
    __shared__ int s[1024];
    const int T = 1024;
    const int C = (N_NODES + T - 1) / T;    // 49
    int t = threadIdx.x;
    int base = t * C;

    int sum = 0;
    for (int i = 0; i < C; i++) {
        int n = base + i;
        if (n < N_NODES) sum += g_deg[n] - 1;
    }
    s[t] = sum;
    __syncthreads();
    for (int off = 1; off < T; off <<= 1) {
        int add = (t >= off) ? s[t - off] : 0;
        __syncthreads();
        s[t] += add;
        __syncthreads();
    }
    int run = s[t] - sum;                   // exclusive prefix
    for (int i = 0; i < C; i++) {
        int n = base + i;
        if (n < N_NODES) {
            g_rowstart[n] = run;
            g_cursor[n]   = run;
            g_dinv[n]     = rsqrtf((float)g_deg[n]);
            run += g_deg[n] - 1;
        }
    }
    if (t == T - 1) g_rowstart[N_NODES] = run;   // == N_EDGES
}

// ---------------- CSR fill ---------------------------------------------------
__global__ void k_fill(const int* __restrict__ ei) {
    int e = blockIdx.x * blockDim.x + threadIdx.x;
    if (e >= N_EDGES) return;
    int src = clampi(ei[e]);
    int dst = clampi(ei[N_EDGES + e]);
    float norm = g_dinv[src] * g_dinv[dst];
    int pos = atomicAdd(&g_cursor[dst], 1);
    g_csr_src[pos]  = src;
    g_csr_norm[pos] = norm;
}

// ---------------- tiled SGEMM: T[N,NOUT] = f(A)[N,128] @ W[128,NOUT] --------
template<int NOUT, bool IN_TRANS>
__device__ __forceinline__ void gemm_body(const float* __restrict__ A,
                                          const float* __restrict__ W,
                                          const float* __restrict__ b_in,
                                          float* __restrict__ T)
{
    constexpr int NC = NOUT / 16;   // cols per thread (8 or 4)
    constexpr int KC = 64;          // k-chunk
    __shared__ float As[32][KC + 4];
    __shared__ float Ws[KC][NOUT];

    const int tid = threadIdx.x;
    const int tx  = tid & 15;       // col group
    const int ty  = tid >> 4;       // row group
    const int row0 = blockIdx.x * 32;

    float acc[4][NC];
#pragma unroll
    for (int i = 0; i < 4; i++)
#pragma unroll
        for (int j = 0; j < NC; j++) acc[i][j] = 0.f;

    for (int kc = 0; kc < D_K; kc += KC) {
#pragma unroll
        for (int q = 0; q < 4; q++) {
            int f  = tid + q * 128;
            int r  = f >> 4;
            int kq = f & 15;
            float4 v = make_float4(0.f, 0.f, 0.f, 0.f);
            int grow = row0 + r;
            if (grow < N_NODES)
                v = *(const float4*)&A[(size_t)grow * D_K + kc + kq * 4];
            if constexpr (IN_TRANS) {
                float4 bb = *(const float4*)&b_in[kc + kq * 4];
                v.x = fmaxf(v.x + bb.x, 0.f);
                v.y = fmaxf(v.y + bb.y, 0.f);
                v.z = fmaxf(v.z + bb.z, 0.f);
                v.w = fmaxf(v.w + bb.w, 0.f);
            }
            *(float4*)&As[r][kq * 4] = v;
        }
        {
            const float4* Wg  = (const float4*)&W[(size_t)kc * NOUT];
            float4*       Wsp = (float4*)&Ws[0][0];
            constexpr int WF4 = KC * NOUT / 4;
#pragma unroll
            for (int q = 0; q < WF4 / 128; q++)
                Wsp[tid + q * 128] = Wg[tid + q * 128];
        }
        __syncthreads();

#pragma unroll 8
        for (int k = 0; k < KC; k++) {
            float a0 = As[ty * 4 + 0][k];
            float a1 = As[ty * 4 + 1][k];
            float a2 = As[ty * 4 + 2][k];
            float a3 = As[ty * 4 + 3][k];
#pragma unroll
            for (int j4 = 0; j4 < NC / 4; j4++) {
                float4 w = *(const float4*)&Ws[k][tx * NC + j4 * 4];
                acc[0][j4*4+0] = fmaf(a0, w.x, acc[0][j4*4+0]);
                acc[0][j4*4+1] = fmaf(a0, w.y, acc[0][j4*4+1]);
                acc[0][j4*4+2] = fmaf(a0, w.z, acc[0][j4*4+2]);
                acc[0][j4*4+3] = fmaf(a0, w.w, acc[0][j4*4+3]);
                acc[1][j4*4+0] = fmaf(a1, w.x, acc[1][j4*4+0]);
                acc[1][j4*4+1] = fmaf(a1, w.y, acc[1][j4*4+1]);
                acc[1][j4*4+2] = fmaf(a1, w.z, acc[1][j4*4+2]);
                acc[1][j4*4+3] = fmaf(a1, w.w, acc[1][j4*4+3]);
                acc[2][j4*4+0] = fmaf(a2, w.x, acc[2][j4*4+0]);
                acc[2][j4*4+1] = fmaf(a2, w.y, acc[2][j4*4+1]);
                acc[2][j4*4+2] = fmaf(a2, w.z, acc[2][j4*4+2]);
                acc[2][j4*4+3] = fmaf(a2, w.w, acc[2][j4*4+3]);
                acc[3][j4*4+0] = fmaf(a3, w.x, acc[3][j4*4+0]);
                acc[3][j4*4+1] = fmaf(a3, w.y, acc[3][j4*4+1]);
                acc[3][j4*4+2] = fmaf(a3, w.z, acc[3][j4*4+2]);
                acc[3][j4*4+3] = fmaf(a3, w.w, acc[3][j4*4+3]);
            }
        }
        __syncthreads();
    }

#pragma unroll
    for (int i = 0; i < 4; i++) {
        int r = row0 + ty * 4 + i;
        if (r >= N_NODES) continue;
#pragma unroll
        for (int j = 0; j < NC; j += 4) {
            float4 t = make_float4(acc[i][j], acc[i][j+1], acc[i][j+2], acc[i][j+3]);
            *(float4*)&T[(size_t)r * NOUT + tx * NC + j] = t;
        }
    }
}

__global__ void __launch_bounds__(128)
k_gemm1(const float* __restrict__ x, const float* __restrict__ W1) {
    gemm_body<D_H1, false>(x, W1, nullptr, g_t1);
}

__global__ void __launch_bounds__(128)
k_gemm2(const float* __restrict__ W2, const float* __restrict__ b1) {
    gemm_body<D_H2, true>(g_agg1, W2, b1, g_t2);
}

// ---------------- layer-1 aggregate: gather, warp per node ------------------
__global__ void k_agg1() {
    int n    = (blockIdx.x * blockDim.x + threadIdx.x) >> 5;
    int lane = threadIdx.x & 31;
    if (n >= N_NODES) return;

    int   s0 = g_rowstart[n];
    int   s1 = g_rowstart[n + 1];
    float dv = g_dinv[n];
    float sn = dv * dv;

    float4 acc = *(const float4*)&g_t1[(size_t)n * D_H1 + lane * 4];
    acc.x *= sn; acc.y *= sn; acc.z *= sn; acc.w *= sn;

    int e = s0;
    for (; e + 1 < s1; e += 2) {          // 2-way unroll: MLP=2
        int   srcA = g_csr_src[e];
        int   srcB = g_csr_src[e + 1];
        float nmA  = g_csr_norm[e];
        float nmB  = g_csr_norm[e + 1];
        float4 vA = *(const float4*)&g_t1[(size_t)srcA * D_H1 + lane * 4];
        float4 vB = *(const float4*)&g_t1[(size_t)srcB * D_H1 + lane * 4];
        acc.x = fmaf(vA.x, nmA, acc.x);
        acc.y = fmaf(vA.y, nmA, acc.y);
        acc.z = fmaf(vA.z, nmA, acc.z);
        acc.w = fmaf(vA.w, nmA, acc.w);
        acc.x = fmaf(vB.x, nmB, acc.x);
        acc.y = fmaf(vB.y, nmB, acc.y);
        acc.z = fmaf(vB.z, nmB, acc.z);
        acc.w = fmaf(vB.w, nmB, acc.w);
    }
    if (e < s1) {
        int   src = g_csr_src[e];
        float nm  = g_csr_norm[e];
        float4 v = *(const float4*)&g_t1[(size_t)src * D_H1 + lane * 4];
        acc.x = fmaf(v.x, nm, acc.x);
        acc.y = fmaf(v.y, nm, acc.y);
        acc.z = fmaf(v.z, nm, acc.z);
        acc.w = fmaf(v.w, nm, acc.w);
    }
    *(float4*)&g_agg1[(size_t)n * D_H1 + lane * 4] = acc;
}

// ---------------- layer-2 aggregate fused with final GEMV -------------------
__global__ void k_agg2_final(const float* __restrict__ b2,
                             const float* __restrict__ W3,
                             const float* __restrict__ b3,
                             float* __restrict__ out)
{
    int n    = (blockIdx.x * blockDim.x + threadIdx.x) >> 5;
    int lane = threadIdx.x & 31;
    if (n >= N_NODES) return;

    int   s0 = g_rowstart[n];
    int   s1 = g_rowstart[n + 1];
    float dv = g_dinv[n];
    float sn = dv * dv;

    float2 acc = *(const float2*)&g_t2[(size_t)n * D_H2 + lane * 2];
    acc.x *= sn; acc.y *= sn;

    int e = s0;
    for (; e + 1 < s1; e += 2) {
        int   srcA = g_csr_src[e];
        int   srcB = g_csr_src[e + 1];
        float nmA  = g_csr_norm[e];
        float nmB  = g_csr_norm[e + 1];
        float2 vA = *(const float2*)&g_t2[(size_t)srcA * D_H2 + lane * 2];
        float2 vB = *(const float2*)&g_t2[(size_t)srcB * D_H2 + lane * 2];
        acc.x = fmaf(vA.x, nmA, acc.x);
        acc.y = fmaf(vA.y, nmA, acc.y);
        acc.x = fmaf(vB.x, nmB, acc.x);
        acc.y = fmaf(vB.y, nmB, acc.y);
    }
    if (e < s1) {
        int   src = g_csr_src[e];
        float nm  = g_csr_norm[e];
        float2 v = *(const float2*)&g_t2[(size_t)src * D_H2 + lane * 2];
        acc.x = fmaf(v.x, nm, acc.x);
        acc.y = fmaf(v.y, nm, acc.y);
    }

    float2 bb = *(const float2*)&b2[lane * 2];
    float2 w  = *(const float2*)&W3[lane * 2];
    float h0 = fmaxf(acc.x + bb.x, 0.f);
    float h1 = fmaxf(acc.y + bb.y, 0.f);
    float s  = fmaf(h0, w.x, h1 * w.y);
#pragma unroll
    for (int o = 16; o; o >>= 1) s += __shfl_xor_sync(0xffffffffu, s, o);
    if (lane == 0) out[n] = s + b3[0];
}

// ---------------- launch -----------------------------------------------------
// CSR build (side stream) runs concurrently with gemm1 (main stream); the two
// join before agg1. Fork/join via events is graph-capture-legal and becomes
// graph edges.
extern "C" void kernel_launch(void* const* d_in, const int* in_sizes, int n_in,
                              void* d_out, int out_size)
{
    const float* x  = (const float*)d_in[0];
    const int*   ei = (const int*)d_in[1];     // int32 edge_index
    const float* W1 = (const float*)d_in[2];
    const float* b1 = (const float*)d_in[3];
    const float* W2 = (const float*)d_in[4];
    const float* b2 = (const float*)d_in[5];
    const float* W3 = (const float*)d_in[6];
    const float* b3 = (const float*)d_in[7];
    float*       out = (float*)d_out;
    (void)in_sizes; (void)n_in; (void)out_size;

    static cudaStream_t s_side = nullptr;
    static cudaEvent_t  e_fork = nullptr, e_join = nullptr;
    if (!s_side) {
        cudaStreamCreateWithFlags(&s_side, cudaStreamNonBlocking);
        cudaEventCreateWithFlags(&e_fork, cudaEventDisableTiming);
        cudaEventCreateWithFlags(&e_join, cudaEventDisableTiming);
    }

    // fork: side stream inherits capture dependency from main stream
    cudaEventRecord(e_fork, 0);
    cudaStreamWaitEvent(s_side, e_fork, 0);

    // ---- side stream: CSR build ----
    k_init_deg <<<(N_NODES + 255) / 256, 256, 0, s_side>>>();
    k_count_deg<<<(N_EDGES + 255) / 256, 256, 0, s_side>>>(ei);
    k_scan     <<<1, 1024, 0, s_side>>>();
    k_fill     <<<(N_EDGES + 255) / 256, 256, 0, s_side>>>(ei);
    cudaEventRecord(e_join, s_side);

    // ---- main stream: gemm1 (independent of CSR) ----
    k_gemm1<<<(N_NODES + 31) / 32, 128>>>(x, W1);

    // join: agg1 needs both gemm1 (main) and CSR (side)
    cudaStreamWaitEvent(0, e_join, 0);

    k_agg1 <<<(N_NODES * 32 + 255) / 256, 256>>>();
    k_gemm2<<<(N_NODES + 31) / 32, 128>>>(W2, b1);
    k_agg2_final<<<(N_NODES * 32 + 255) / 256, 256>>>(b2, W3, b3, out);
}

// round 6
// speedup vs baseline: 1.2043x; 1.2043x over previous
#include <cuda_runtime.h>
#include <cstdint>

#define N_NODES 50000
#define N_EDGES 600000
#define D_K     128
#define D_H1    128
#define D_H2    64

// ---------------- scratch (device globals: no allocation allowed) ----------
__device__ int   g_deg     [N_NODES];
__device__ float g_dinv    [N_NODES];
__device__ int   g_rowstart[N_NODES + 1];
__device__ int   g_cursor  [N_NODES];
__device__ int   g_csr_src [N_EDGES];
__device__ __align__(16) float g_t1  [N_NODES * D_H1];   // (x @ W1) * dinv[row]
__device__ __align__(16) float g_agg1[N_NODES * D_H1];   // aggregated layer-1
__device__ __align__(16) float g_t2  [N_NODES * D_H2];   // (relu(agg1+b1) @ W2) * dinv[row]

__device__ __forceinline__ int clampi(int v) {
    return min(max(v, 0), N_NODES - 1);
}

// ---------------- degree -----------------------------------------------------
__global__ void k_init_deg() {
    int i = blockIdx.x * blockDim.x + threadIdx.x;
    if (i < N_NODES) g_deg[i] = 1;          // self-loop
}

__global__ void k_count_deg(const int* __restrict__ ei) {
    int e = blockIdx.x * blockDim.x + threadIdx.x;
    if (e < N_EDGES) atomicAdd(&g_deg[clampi(ei[N_EDGES + e])], 1);  // dst
}

// ---------------- single-block scan: rowstart/cursor/dinv -------------------
__global__ void __launch_bounds__(1024) k_scan() {
    __shared__ int s[1024];
    const int T = 1024;
    const int C = (N_NODES + T - 1) / T;    // 49
    int t = threadIdx.x;
    int base = t * C;

    int sum = 0;
    for (int i = 0; i < C; i++) {
        int n = base + i;
        if (n < N_NODES) sum += g_deg[n] - 1;
    }
    s[t] = sum;
    __syncthreads();
    for (int off = 1; off < T; off <<= 1) {
        int add = (t >= off) ? s[t - off] : 0;
        __syncthreads();
        s[t] += add;
        __syncthreads();
    }
    int run = s[t] - sum;                   // exclusive prefix
    for (int i = 0; i < C; i++) {
        int n = base + i;
        if (n < N_NODES) {
            g_rowstart[n] = run;
            g_cursor[n]   = run;
            g_dinv[n]     = rsqrtf((float)g_deg[n]);
            run += g_deg[n] - 1;
        }
    }
    if (t == T - 1) g_rowstart[N_NODES] = run;   // == N_EDGES
}

// ---------------- CSR fill (src only; norm folded into prescaled features) --
__global__ void k_fill(const int* __restrict__ ei) {
    int e = blockIdx.x * blockDim.x + threadIdx.x;
    if (e >= N_EDGES) return;
    int src = clampi(ei[e]);
    int dst = clampi(ei[N_EDGES + e]);
    int pos = atomicAdd(&g_cursor[dst], 1);
    g_csr_src[pos] = src;
}

// ---------------- tiled SGEMM: T[N,NOUT] = (f(A)[N,128] @ W) * dinv[row] ----
template<int NOUT, bool IN_TRANS>
__device__ __forceinline__ void gemm_body(const float* __restrict__ A,
                                          const float* __restrict__ W,
                                          const float* __restrict__ b_in,
                                          float* __restrict__ T)
{
    constexpr int NC = NOUT / 16;   // cols per thread (8 or 4)
    constexpr int KC = 64;          // k-chunk
    __shared__ float As[32][KC + 4];
    __shared__ float Ws[KC][NOUT];

    const int tid = threadIdx.x;
    const int tx  = tid & 15;       // col group
    const int ty  = tid >> 4;       // row group
    const int row0 = blockIdx.x * 32;

    float acc[4][NC];
#pragma unroll
    for (int i = 0; i < 4; i++)
#pragma unroll
        for (int j = 0; j < NC; j++) acc[i][j] = 0.f;

    for (int kc = 0; kc < D_K; kc += KC) {
#pragma unroll
        for (int q = 0; q < 4; q++) {
            int f  = tid + q * 128;
            int r  = f >> 4;
            int kq = f & 15;
            float4 v = make_float4(0.f, 0.f, 0.f, 0.f);
            int grow = row0 + r;
            if (grow < N_NODES)
                v = *(const float4*)&A[(size_t)grow * D_K + kc + kq * 4];
            if constexpr (IN_TRANS) {
                float4 bb = *(const float4*)&b_in[kc + kq * 4];
                v.x = fmaxf(v.x + bb.x, 0.f);
                v.y = fmaxf(v.y + bb.y, 0.f);
                v.z = fmaxf(v.z + bb.z, 0.f);
                v.w = fmaxf(v.w + bb.w, 0.f);
            }
            *(float4*)&As[r][kq * 4] = v;
        }
        {
            const float4* Wg  = (const float4*)&W[(size_t)kc * NOUT];
            float4*       Wsp = (float4*)&Ws[0][0];
            constexpr int WF4 = KC * NOUT / 4;
#pragma unroll
            for (int q = 0; q < WF4 / 128; q++)
                Wsp[tid + q * 128] = Wg[tid + q * 128];
        }
        __syncthreads();

#pragma unroll 8
        for (int k = 0; k < KC; k++) {
            float a0 = As[ty * 4 + 0][k];
            float a1 = As[ty * 4 + 1][k];
            float a2 = As[ty * 4 + 2][k];
            float a3 = As[ty * 4 + 3][k];
#pragma unroll
            for (int j4 = 0; j4 < NC / 4; j4++) {
                float4 w = *(const float4*)&Ws[k][tx * NC + j4 * 4];
                acc[0][j4*4+0] = fmaf(a0, w.x, acc[0][j4*4+0]);
                acc[0][j4*4+1] = fmaf(a0, w.y, acc[0][j4*4+1]);
                acc[0][j4*4+2] = fmaf(a0, w.z, acc[0][j4*4+2]);
                acc[0][j4*4+3] = fmaf(a0, w.w, acc[0][j4*4+3]);
                acc[1][j4*4+0] = fmaf(a1, w.x, acc[1][j4*4+0]);
                acc[1][j4*4+1] = fmaf(a1, w.y, acc[1][j4*4+1]);
                acc[1][j4*4+2] = fmaf(a1, w.z, acc[1][j4*4+2]);
                acc[1][j4*4+3] = fmaf(a1, w.w, acc[1][j4*4+3]);
                acc[2][j4*4+0] = fmaf(a2, w.x, acc[2][j4*4+0]);
                acc[2][j4*4+1] = fmaf(a2, w.y, acc[2][j4*4+1]);
                acc[2][j4*4+2] = fmaf(a2, w.z, acc[2][j4*4+2]);
                acc[2][j4*4+3] = fmaf(a2, w.w, acc[2][j4*4+3]);
                acc[3][j4*4+0] = fmaf(a3, w.x, acc[3][j4*4+0]);
                acc[3][j4*4+1] = fmaf(a3, w.y, acc[3][j4*4+1]);
                acc[3][j4*4+2] = fmaf(a3, w.z, acc[3][j4*4+2]);
                acc[3][j4*4+3] = fmaf(a3, w.w, acc[3][j4*4+3]);
            }
        }
        __syncthreads();
    }

    // epilogue: prescale by dinv[row] so gathers need no per-edge norm
#pragma unroll
    for (int i = 0; i < 4; i++) {
        int r = row0 + ty * 4 + i;
        if (r >= N_NODES) continue;
        float dv = g_dinv[r];
#pragma unroll
        for (int j = 0; j < NC; j += 4) {
            float4 t = make_float4(acc[i][j] * dv, acc[i][j+1] * dv,
                                   acc[i][j+2] * dv, acc[i][j+3] * dv);
            *(float4*)&T[(size_t)r * NOUT + tx * NC + j] = t;
        }
    }
}

__global__ void __launch_bounds__(128)
k_gemm1(const float* __restrict__ x, const float* __restrict__ W1) {
    gemm_body<D_H1, false>(x, W1, nullptr, g_t1);
}

__global__ void __launch_bounds__(128)
k_gemm2(const float* __restrict__ W2, const float* __restrict__ b1) {
    gemm_body<D_H2, true>(g_agg1, W2, b1, g_t2);
}

// ---------------- layer-1 aggregate: gather, warp per node ------------------
// agg1[n] = dinv[n] * ( t1'[n] + sum_{e: dst=n} t1'[src_e] ),  t1' prescaled
__global__ void k_agg1() {
    int n    = (blockIdx.x * blockDim.x + threadIdx.x) >> 5;
    int lane = threadIdx.x & 31;
    if (n >= N_NODES) return;

    int   s0 = g_rowstart[n];
    int   s1 = g_rowstart[n + 1];
    float dv = g_dinv[n];

    float4 acc = *(const float4*)&g_t1[(size_t)n * D_H1 + lane * 4];

    int e = s0;
    for (; e + 1 < s1; e += 2) {          // 2-way unroll: MLP=2
        int srcA = g_csr_src[e];
        int srcB = g_csr_src[e + 1];
        float4 vA = *(const float4*)&g_t1[(size_t)srcA * D_H1 + lane * 4];
        float4 vB = *(const float4*)&g_t1[(size_t)srcB * D_H1 + lane * 4];
        acc.x += vA.x + vB.x;
        acc.y += vA.y + vB.y;
        acc.z += vA.z + vB.z;
        acc.w += vA.w + vB.w;
    }
    if (e < s1) {
        int src = g_csr_src[e];
        float4 v = *(const float4*)&g_t1[(size_t)src * D_H1 + lane * 4];
        acc.x += v.x; acc.y += v.y; acc.z += v.z; acc.w += v.w;
    }
    acc.x *= dv; acc.y *= dv; acc.z *= dv; acc.w *= dv;
    *(float4*)&g_agg1[(size_t)n * D_H1 + lane * 4] = acc;
}

// ---------------- layer-2 aggregate fused with final GEMV -------------------
// out[n] = relu(dinv[n]*(t2'[n]+sum t2'[src]) + b2) . W3 + b3
__global__ void k_agg2_final(const float* __restrict__ b2,
                             const float* __restrict__ W3,
                             const float* __restrict__ b3,
                             float* __restrict__ out)
{
    int n    = (blockIdx.x * blockDim.x + threadIdx.x) >> 5;
    int lane = threadIdx.x & 31;
    if (n >= N_NODES) return;

    int   s0 = g_rowstart[n];
    int   s1 = g_rowstart[n + 1];
    float dv = g_dinv[n];

    float2 acc = *(const float2*)&g_t2[(size_t)n * D_H2 + lane * 2];

    int e = s0;
    for (; e + 1 < s1; e += 2) {
        int srcA = g_csr_src[e];
        int srcB = g_csr_src[e + 1];
        float2 vA = *(const float2*)&g_t2[(size_t)srcA * D_H2 + lane * 2];
        float2 vB = *(const float2*)&g_t2[(size_t)srcB * D_H2 + lane * 2];
        acc.x += vA.x + vB.x;
        acc.y += vA.y + vB.y;
    }
    if (e < s1) {
        int src = g_csr_src[e];
        float2 v = *(const float2*)&g_t2[(size_t)src * D_H2 + lane * 2];
        acc.x += v.x; acc.y += v.y;
    }
    acc.x *= dv; acc.y *= dv;

    float2 bb = *(const float2*)&b2[lane * 2];
    float2 w  = *(const float2*)&W3[lane * 2];
    float h0 = fmaxf(acc.x + bb.x, 0.f);
    float h1 = fmaxf(acc.y + bb.y, 0.f);
    float s  = fmaf(h0, w.x, h1 * w.y);
#pragma unroll
    for (int o = 16; o; o >>= 1) s += __shfl_xor_sync(0xffffffffu, s, o);
    if (lane == 0) out[n] = s + b3[0];
}

// ---------------- launch (single stream — R5 showed forking regresses) ------
extern "C" void kernel_launch(void* const* d_in, const int* in_sizes, int n_in,
                              void* d_out, int out_size)
{
    const float* x  = (const float*)d_in[0];
    const int*   ei = (const int*)d_in[1];     // int32 edge_index
    const float* W1 = (const float*)d_in[2];
    const float* b1 = (const float*)d_in[3];
    const float* W2 = (const float*)d_in[4];
    const float* b2 = (const float*)d_in[5];
    const float* W3 = (const float*)d_in[6];
    const float* b3 = (const float*)d_in[7];
    float*       out = (float*)d_out;
    (void)in_sizes; (void)n_in; (void)out_size;

    k_init_deg <<<(N_NODES + 255) / 256, 256>>>();
    k_count_deg<<<(N_EDGES + 255) / 256, 256>>>(ei);
    k_scan     <<<1, 1024>>>();
    k_fill     <<<(N_EDGES + 255) / 256, 256>>>(ei);

    k_gemm1<<<(N_NODES + 31) / 32, 128>>>(x, W1);
    k_agg1 <<<(N_NODES * 32 + 255) / 256, 256>>>();

    k_gemm2<<<(N_NODES + 31) / 32, 128>>>(W2, b1);
    k_agg2_final<<<(N_NODES * 32 + 255) / 256, 256>>>(b2, W3, b3, out);
}